// round 14
// baseline (speedup 1.0000x reference)
#include <cuda_runtime.h>
#include <cuda_bf16.h>
#include <cstdint>

// ---------------- problem constants ----------------
#define NPAIRS 4096
#define TWO_N  8192
#define DIM    256
#define NT     64          // 8192/128 tiles per side
#define NTRI   2080        // NT*(NT+1)/2 upper-triangular tiles
#define COS_EPS 1e-8f
// exp(2*s) = 2^(s * 2/ln2)
#define EX2_SCALE 2.8853900817779268f

// ---------------- scratch (device globals, no allocation) ----------------
__device__ __align__(256) uint32_t g_nhat[TWO_N * DIM / 4]; // normalized reps, e4m3 (2MB)
__device__ float g_rowsum[TWO_N];
__device__ float g_pos[NPAIRS];
__device__ unsigned int g_done;                              // reset by k_norm each launch

// ---------------- PTX helpers (sm_103 base target: ldmatrix + legacy mma + cp.async) -
__device__ __forceinline__ uint32_t smem_u32(const void* p) {
    uint32_t a;
    asm("{ .reg .u64 t; cvta.to.shared.u64 t, %1; cvt.u32.u64 %0, t; }" : "=r"(a) : "l"(p));
    return a;
}

__device__ __forceinline__ void ldsm_x4(uint32_t addr, uint32_t* r) {
    asm volatile("ldmatrix.sync.aligned.m8n8.x4.shared.b16 {%0,%1,%2,%3}, [%4];"
        : "=r"(r[0]), "=r"(r[1]), "=r"(r[2]), "=r"(r[3]) : "r"(addr));
}

// fp8 e4m3 MMA: fragment byte-layout matches b16 ldmatrix loads exactly.
__device__ __forceinline__ void mma16832_e4m3(float* d, const uint32_t* a, const uint32_t* b) {
    asm volatile("mma.sync.aligned.m16n8k32.row.col.f32.e4m3.e4m3.f32 "
        "{%0,%1,%2,%3}, {%4,%5,%6,%7}, {%8,%9}, {%0,%1,%2,%3};"
        : "+f"(d[0]), "+f"(d[1]), "+f"(d[2]), "+f"(d[3])
        : "r"(a[0]), "r"(a[1]), "r"(a[2]), "r"(a[3]), "r"(b[0]), "r"(b[1]));
}

__device__ __forceinline__ void cp_async16(uint32_t dst, const void* src) {
    asm volatile("cp.async.ca.shared.global [%0], [%1], 16;" :: "r"(dst), "l"(src) : "memory");
}

__device__ __forceinline__ float ex2f(float x) {
    float r;
    asm("ex2.approx.f32 %0, %1;" : "=f"(r) : "f"(x));
    return r;
}

__device__ __forceinline__ uint32_t pack_e4m3x4(float x0, float x1, float x2, float x3) {
    uint16_t lo, hi;
    asm("cvt.rn.satfinite.e4m3x2.f32 %0, %1, %2;" : "=h"(lo) : "f"(x1), "f"(x0));
    asm("cvt.rn.satfinite.e4m3x2.f32 %0, %1, %2;" : "=h"(hi) : "f"(x3), "f"(x2));
    return (uint32_t)lo | ((uint32_t)hi << 16);
}

// ---------------- kernel 1: normalize + positives (fp32, exact) + scratch reset -----
__global__ void k_norm(const float* __restrict__ zis, const float* __restrict__ zjs) {
    int tid = threadIdx.x;
    int gid = blockIdx.x * 256 + tid;
    if (gid < TWO_N) g_rowsum[gid] = 0.0f;
    if (gid == 0) g_done = 0u;

    int w = blockIdx.x * 8 + (tid >> 5);   // pair index 0..4095
    int lane = tid & 31;

    const float4* zi = (const float4*)zis + (size_t)w * 64;
    const float4* zj = (const float4*)zjs + (size_t)w * 64;
    float4 a0 = zi[lane], a1 = zi[lane + 32];
    float4 b0 = zj[lane], b1 = zj[lane + 32];

    float si = a0.x*a0.x + a0.y*a0.y + a0.z*a0.z + a0.w*a0.w
             + a1.x*a1.x + a1.y*a1.y + a1.z*a1.z + a1.w*a1.w;
    float sj = b0.x*b0.x + b0.y*b0.y + b0.z*b0.z + b0.w*b0.w
             + b1.x*b1.x + b1.y*b1.y + b1.z*b1.z + b1.w*b1.w;
    float dv = a0.x*b0.x + a0.y*b0.y + a0.z*b0.z + a0.w*b0.w
             + a1.x*b1.x + a1.y*b1.y + a1.z*b1.z + a1.w*b1.w;
    #pragma unroll
    for (int o = 16; o; o >>= 1) {
        si += __shfl_xor_sync(0xFFFFFFFFu, si, o);
        sj += __shfl_xor_sync(0xFFFFFFFFu, sj, o);
        dv += __shfl_xor_sync(0xFFFFFFFFu, dv, o);
    }
    float ni = sqrtf(si), nj = sqrtf(sj);
    if (lane == 0) g_pos[w] = dv / fmaxf(ni * nj, COS_EPS);

    float ii = 1.0f / ni, ji = 1.0f / nj;
    // reps = [zjs ; zis]: row w <- zjs[w]/nj, row w+NPAIRS <- zis[w]/ni  (e4m3)
    uint32_t* rj = g_nhat + (size_t)w * 64;
    uint32_t* ri = g_nhat + (size_t)(w + NPAIRS) * 64;
    rj[lane]      = pack_e4m3x4(b0.x*ji, b0.y*ji, b0.z*ji, b0.w*ji);
    rj[lane + 32] = pack_e4m3x4(b1.x*ji, b1.y*ji, b1.z*ji, b1.w*ji);
    ri[lane]      = pack_e4m3x4(a0.x*ii, a0.y*ii, a0.z*ii, a0.w*ii);
    ri[lane + 32] = pack_e4m3x4(a1.x*ii, a1.y*ii, a1.z*ii, a1.w*ii);
}

// ---------------- kernel 2: symmetric fp8 mma GEMM tile + exp + partial sums + tail -
// R12 proven body: triangular tiles tm<=tn, 256 threads, warp grid 2(m)x4(n),
// warp tile 64x32, 2-stage split-K cp.async, hoisted diag branch, ex2 epilogue.
// NEW: last-CTA-done fused final reduction (threadFenceReduction pattern).
static constexpr uint32_t TILEB = 128u * 256u;      // 32 KB per tile
static constexpr uint32_t SMEM_TOTAL = 2u * TILEB;  // 64 KB -> occupancy 2

__global__ __launch_bounds__(256, 2) void k_gemm(float* __restrict__ out) {
    extern __shared__ uint8_t smem[];
    __shared__ unsigned int lastFlag;
    __shared__ float sh[8];

    // triangular decode: linear t -> (tm, tn), tm <= tn
    int t = blockIdx.x;
    int tm = (int)(64.5f - sqrtf(64.5f * 64.5f - 2.0f * (float)t));
    while (NT * tm - tm * (tm - 1) / 2 > t) --tm;
    while (NT * (tm + 1) - (tm + 1) * tm / 2 <= t) ++tm;
    int tn = tm + (t - (NT * tm - tm * (tm - 1) / 2));

    int tid = threadIdx.x, wid = tid >> 5, lane = tid & 31;
    int wm = wid >> 2, wn = wid & 3;         // warp grid 2(m) x 4(n); warp tile 64x32
    int g = lane >> 2, q = lane & 3;
    bool diag = (tm == tn);

    uint32_t sbase = smem_u32(smem);

    // ---- global -> shared via cp.async, split-K double commit (K halves) ----
    const uint4* __restrict__ src = (const uint4*)g_nhat; // 16 x 16B chunks per row
    #pragma unroll
    for (int h = 0; h < 2; ++h) {
        #pragma unroll
        for (int it = 0; it < 4; ++it) {     // 128 rows x 8 chunks per half per tile
            int idx = it * 256 + tid;        // 0..1023
            int r = idx >> 3, kv = (idx & 7) + h * 8;
            uint32_t off = (uint32_t)(r * 256 + kv * 16);
            uint32_t sw = off ^ ((uint32_t)(r & 7) << 4);
            cp_async16(sbase + sw, src + (size_t)(tm * 128 + r) * 16 + kv);
            if (!diag)
                cp_async16(sbase + TILEB + sw, src + (size_t)(tn * 128 + r) * 16 + kv);
        }
        asm volatile("cp.async.commit_group;" ::: "memory");
    }

    uint32_t sA = sbase;
    uint32_t sB = diag ? sA : (sA + TILEB);

    float acc[4][4][4];
    #pragma unroll
    for (int i = 0; i < 4; ++i)
        #pragma unroll
        for (int j = 0; j < 4; ++j)
            #pragma unroll
            for (int x = 0; x < 4; ++x) acc[i][j][x] = 0.f;

    int l7 = lane & 7;
    int ra_base = wm * 64 + l7 + ((lane >> 3) & 1) * 8;  // A rows
    int ka_base = (lane >> 4) * 16;                      // A 16B sub-chunk of 32B k-step
    int rb_base = wn * 32 + l7 + (lane >> 4) * 8;        // B n-rows
    int kb_base = ((lane >> 3) & 1) * 16;                // B 16B sub-chunk

    #pragma unroll
    for (int half = 0; half < 2; ++half) {
        if (half == 0) asm volatile("cp.async.wait_group 1;" ::: "memory");
        else           asm volatile("cp.async.wait_group 0;" ::: "memory");
        __syncthreads();
        #pragma unroll
        for (int k2 = 0; k2 < 4; ++k2) {                 // k-step = 32 fp8 = 32 bytes
            int kk = half * 4 + k2;
            uint32_t af[4][4];
            #pragma unroll
            for (int i = 0; i < 4; ++i) {
                int r = ra_base + i * 16;
                uint32_t off = (uint32_t)(r * 256 + kk * 32 + ka_base);
                ldsm_x4(sA + (off ^ ((uint32_t)(r & 7) << 4)), af[i]);
            }
            uint32_t bf[2][4];
            #pragma unroll
            for (int j2 = 0; j2 < 2; ++j2) {
                int r = rb_base + j2 * 16;
                uint32_t off = (uint32_t)(r * 256 + kk * 32 + kb_base);
                ldsm_x4(sB + (off ^ ((uint32_t)(r & 7) << 4)), bf[j2]);
            }
            #pragma unroll
            for (int i = 0; i < 4; ++i)
                #pragma unroll
                for (int j = 0; j < 4; ++j)
                    mma16832_e4m3(acc[i][j], af[i], &bf[j >> 1][(j & 1) * 2]);
        }
    }
    __syncthreads();   // smem tiles no longer needed; reuse for reductions

    float* rAcc = (float*)smem;        // 128 row partials (tm rows)
    float* cAcc = rAcc + 128;          // 128 col partials (tn rows, via symmetry)
    ((float*)smem)[tid] = 0.f;
    __syncthreads();

    float rs[4][2], cs[4][2];
    #pragma unroll
    for (int i = 0; i < 4; ++i) { rs[i][0] = 0.f; rs[i][1] = 0.f; }
    #pragma unroll
    for (int j = 0; j < 4; ++j) { cs[j][0] = 0.f; cs[j][1] = 0.f; }

    if (!diag) {
        // ---- hot path (97% of tiles): no masking, no compares ----
        #pragma unroll
        for (int i = 0; i < 4; ++i) {
            #pragma unroll
            for (int j = 0; j < 4; ++j) {
                float e00 = ex2f(EX2_SCALE * acc[i][j][0]);
                float e01 = ex2f(EX2_SCALE * acc[i][j][1]);
                float e10 = ex2f(EX2_SCALE * acc[i][j][2]);
                float e11 = ex2f(EX2_SCALE * acc[i][j][3]);
                rs[i][0] += e00 + e01;  rs[i][1] += e10 + e11;
                cs[j][0] += e00 + e10;  cs[j][1] += e01 + e11;
            }
        }
    } else {
        // ---- diagonal tiles (64 of 2080): mask self-diagonal, rows only ----
        #pragma unroll
        for (int i = 0; i < 4; ++i) {
            int R0 = wm * 64 + i * 16 + g, R1 = R0 + 8;
            #pragma unroll
            for (int j = 0; j < 4; ++j) {
                int C0 = wn * 32 + j * 8 + 2 * q, C1 = C0 + 1;
                float e00 = ex2f(EX2_SCALE * acc[i][j][0]);
                float e01 = ex2f(EX2_SCALE * acc[i][j][1]);
                float e10 = ex2f(EX2_SCALE * acc[i][j][2]);
                float e11 = ex2f(EX2_SCALE * acc[i][j][3]);
                if (R0 == C0) e00 = 0.f;
                if (R0 == C1) e01 = 0.f;
                if (R1 == C0) e10 = 0.f;
                if (R1 == C1) e11 = 0.f;
                rs[i][0] += e00 + e01;  rs[i][1] += e10 + e11;
            }
        }
    }
    // row partials: lanes sharing g share rows -> reduce over q
    #pragma unroll
    for (int i = 0; i < 4; ++i)
        #pragma unroll
        for (int h = 0; h < 2; ++h) {
            float v = rs[i][h];
            v += __shfl_xor_sync(0xFFFFFFFFu, v, 1);
            v += __shfl_xor_sync(0xFFFFFFFFu, v, 2);
            if (q == 0) atomicAdd(&rAcc[wm * 64 + i * 16 + g + h * 8], v);
        }
    // col partials: lanes sharing q share cols -> reduce over g (off-diagonal tiles)
    if (!diag) {
        #pragma unroll
        for (int j = 0; j < 4; ++j)
            #pragma unroll
            for (int h = 0; h < 2; ++h) {
                float v = cs[j][h];
                v += __shfl_xor_sync(0xFFFFFFFFu, v, 4);
                v += __shfl_xor_sync(0xFFFFFFFFu, v, 8);
                v += __shfl_xor_sync(0xFFFFFFFFu, v, 16);
                if (g == 0) atomicAdd(&cAcc[wn * 32 + j * 8 + 2 * q + h], v);
            }
    }
    __syncthreads();
    if (tid < 128) {
        atomicAdd(&g_rowsum[tm * 128 + tid], rAcc[tid]);
        if (!diag) atomicAdd(&g_rowsum[tn * 128 + tid], cAcc[tid]);
    }

    // ---- last-CTA-done fused tail (threadFenceReduction pattern) ----
    __threadfence();                         // release: rowsum atomics visible gpu-wide
    __syncthreads();
    if (tid == 0)
        lastFlag = (atomicAdd(&g_done, 1u) == NTRI - 1u) ? 1u : 0u;
    __syncthreads();
    if (lastFlag) {
        __threadfence();                     // acquire: observe all CTAs' atomics
        float v = 0.f;
        #pragma unroll
        for (int it = 0; it < 32; ++it) {
            int r = tid + it * 256;
            v += __logf(g_rowsum[r]) - 2.0f * g_pos[r & (NPAIRS - 1)];
        }
        #pragma unroll
        for (int o = 16; o; o >>= 1) v += __shfl_xor_sync(0xFFFFFFFFu, v, o);
        if (lane == 0) sh[wid] = v;
        __syncthreads();
        if (tid == 0) {
            float s = sh[0] + sh[1] + sh[2] + sh[3]
                    + sh[4] + sh[5] + sh[6] + sh[7];
            out[0] = s / (float)TWO_N;
        }
    }
}

// ---------------- launch ----------------
extern "C" void kernel_launch(void* const* d_in, const int* in_sizes, int n_in,
                              void* d_out, int out_size) {
    const float* zis = (const float*)d_in[0];
    const float* zjs = (const float*)d_in[1];
    float* out = (float*)d_out;

    cudaFuncSetAttribute(k_gemm, cudaFuncAttributeMaxDynamicSharedMemorySize, SMEM_TOTAL);

    k_norm<<<512, 256>>>(zis, zjs);
    k_gemm<<<NTRI, 256, SMEM_TOTAL>>>(out);
}

// round 15
// speedup vs baseline: 1.1481x; 1.1481x over previous
#include <cuda_runtime.h>
#include <cuda_bf16.h>
#include <cstdint>

// ---------------- problem constants ----------------
#define NPAIRS 4096
#define TWO_N  8192
#define DIM    256
#define NT     64          // 8192/128 tiles per side
#define NTRI   2080        // NT*(NT+1)/2 upper-triangular tiles
#define COS_EPS 1e-8f
// exp(2*s) = 2^(s * 2/ln2); sqrt of that scale folded into each normalized factor
#define EX2_SQRT_SCALE 1.6986436f

// ---------------- scratch (device globals, no allocation) ----------------
__device__ __align__(256) uint32_t g_nhat[TWO_N * DIM / 4]; // scaled normalized reps, e4m3
__device__ float g_rowsum[TWO_N];
__device__ float g_pos[NPAIRS];

// ---------------- PTX helpers (sm_103 base target: ldmatrix + legacy mma + cp.async) -
__device__ __forceinline__ uint32_t smem_u32(const void* p) {
    uint32_t a;
    asm("{ .reg .u64 t; cvta.to.shared.u64 t, %1; cvt.u32.u64 %0, t; }" : "=r"(a) : "l"(p));
    return a;
}

__device__ __forceinline__ void ldsm_x4(uint32_t addr, uint32_t* r) {
    asm volatile("ldmatrix.sync.aligned.m8n8.x4.shared.b16 {%0,%1,%2,%3}, [%4];"
        : "=r"(r[0]), "=r"(r[1]), "=r"(r[2]), "=r"(r[3]) : "r"(addr));
}

// fp8 e4m3 MMA: fragment byte-layout matches b16 ldmatrix loads exactly.
__device__ __forceinline__ void mma16832_e4m3(float* d, const uint32_t* a, const uint32_t* b) {
    asm volatile("mma.sync.aligned.m16n8k32.row.col.f32.e4m3.e4m3.f32 "
        "{%0,%1,%2,%3}, {%4,%5,%6,%7}, {%8,%9}, {%0,%1,%2,%3};"
        : "+f"(d[0]), "+f"(d[1]), "+f"(d[2]), "+f"(d[3])
        : "r"(a[0]), "r"(a[1]), "r"(a[2]), "r"(a[3]), "r"(b[0]), "r"(b[1]));
}

__device__ __forceinline__ void cp_async16(uint32_t dst, const void* src) {
    asm volatile("cp.async.ca.shared.global [%0], [%1], 16;" :: "r"(dst), "l"(src) : "memory");
}

__device__ __forceinline__ float ex2f(float x) {
    float r;
    asm("ex2.approx.f32 %0, %1;" : "=f"(r) : "f"(x));
    return r;
}

// pack two f32 -> f16x2 (lo, hi)
__device__ __forceinline__ uint32_t packh2(float lo, float hi) {
    uint32_t r;
    asm("cvt.rn.f16x2.f32 %0, %1, %2;" : "=r"(r) : "f"(hi), "f"(lo));
    return r;
}
__device__ __forceinline__ uint32_t h2ex2(uint32_t x) {
    uint32_t r;
    asm("ex2.approx.f16x2 %0, %1;" : "=r"(r) : "r"(x));
    return r;
}
__device__ __forceinline__ uint32_t hadd2(uint32_t a, uint32_t b) {
    uint32_t r;
    asm("add.rn.f16x2 %0, %1, %2;" : "=r"(r) : "r"(a), "r"(b));
    return r;
}
__device__ __forceinline__ void unpackh2(uint32_t p, float& lo, float& hi) {
    asm("{.reg .f16 l, h;\n\t mov.b32 {l, h}, %2;\n\t cvt.f32.f16 %0, l;\n\t cvt.f32.f16 %1, h;}"
        : "=f"(lo), "=f"(hi) : "r"(p));
}

__device__ __forceinline__ uint32_t pack_e4m3x4(float x0, float x1, float x2, float x3) {
    uint16_t lo, hi;
    asm("cvt.rn.satfinite.e4m3x2.f32 %0, %1, %2;" : "=h"(lo) : "f"(x1), "f"(x0));
    asm("cvt.rn.satfinite.e4m3x2.f32 %0, %1, %2;" : "=h"(hi) : "f"(x3), "f"(x2));
    return (uint32_t)lo | ((uint32_t)hi << 16);
}

// ---------------- kernel 1: normalize (x ex2-sqrt-scale) + positives + rowsum zero ---
__global__ void k_norm(const float* __restrict__ zis, const float* __restrict__ zjs) {
    int tid = threadIdx.x;
    int gid = blockIdx.x * 256 + tid;
    if (gid < TWO_N) g_rowsum[gid] = 0.0f;

    int w = blockIdx.x * 8 + (tid >> 5);   // pair index 0..4095
    int lane = tid & 31;

    const float4* zi = (const float4*)zis + (size_t)w * 64;
    const float4* zj = (const float4*)zjs + (size_t)w * 64;
    float4 a0 = zi[lane], a1 = zi[lane + 32];
    float4 b0 = zj[lane], b1 = zj[lane + 32];

    float si = a0.x*a0.x + a0.y*a0.y + a0.z*a0.z + a0.w*a0.w
             + a1.x*a1.x + a1.y*a1.y + a1.z*a1.z + a1.w*a1.w;
    float sj = b0.x*b0.x + b0.y*b0.y + b0.z*b0.z + b0.w*b0.w
             + b1.x*b1.x + b1.y*b1.y + b1.z*b1.z + b1.w*b1.w;
    float dv = a0.x*b0.x + a0.y*b0.y + a0.z*b0.z + a0.w*b0.w
             + a1.x*b1.x + a1.y*b1.y + a1.z*b1.z + a1.w*b1.w;
    #pragma unroll
    for (int o = 16; o; o >>= 1) {
        si += __shfl_xor_sync(0xFFFFFFFFu, si, o);
        sj += __shfl_xor_sync(0xFFFFFFFFu, sj, o);
        dv += __shfl_xor_sync(0xFFFFFFFFu, dv, o);
    }
    float ni = sqrtf(si), nj = sqrtf(sj);
    if (lane == 0) g_pos[w] = dv / fmaxf(ni * nj, COS_EPS);   // exact fp32 positive

    // fold sqrt(2/T * log2e) into each factor: acc = (2/T)*log2e * s directly
    float ii = EX2_SQRT_SCALE / ni, ji = EX2_SQRT_SCALE / nj;
    uint32_t* rj = g_nhat + (size_t)w * 64;
    uint32_t* ri = g_nhat + (size_t)(w + NPAIRS) * 64;
    rj[lane]      = pack_e4m3x4(b0.x*ji, b0.y*ji, b0.z*ji, b0.w*ji);
    rj[lane + 32] = pack_e4m3x4(b1.x*ji, b1.y*ji, b1.z*ji, b1.w*ji);
    ri[lane]      = pack_e4m3x4(a0.x*ii, a0.y*ii, a0.z*ii, a0.w*ii);
    ri[lane + 32] = pack_e4m3x4(a1.x*ii, a1.y*ii, a1.z*ii, a1.w*ii);
}

// ---------------- kernel 2: symmetric fp8 mma GEMM tile + f16x2 exp + partial sums ---
// R12 proven shape: triangular tiles tm<=tn, 256 threads, warp grid 2(m)x4(n),
// warp tile 64x32, 2-stage split-K cp.async, swizzle off ^= (r&7)<<4.
// NEW: acc is pre-scaled (2/T*log2e)*s -> epilogue = pack f16x2 + ex2.f16x2 + hadd2.
static constexpr uint32_t TILEB = 128u * 256u;      // 32 KB per tile
static constexpr uint32_t SMEM_TOTAL = 2u * TILEB;  // 64 KB -> occupancy 2

__global__ __launch_bounds__(256, 2) void k_gemm() {
    extern __shared__ uint8_t smem[];
    // triangular decode: linear t -> (tm, tn), tm <= tn
    int t = blockIdx.x;
    int tm = (int)(64.5f - sqrtf(64.5f * 64.5f - 2.0f * (float)t));
    while (NT * tm - tm * (tm - 1) / 2 > t) --tm;
    while (NT * (tm + 1) - (tm + 1) * tm / 2 <= t) ++tm;
    int tn = tm + (t - (NT * tm - tm * (tm - 1) / 2));

    int tid = threadIdx.x, wid = tid >> 5, lane = tid & 31;
    int wm = wid >> 2, wn = wid & 3;         // warp grid 2(m) x 4(n); warp tile 64x32
    int g = lane >> 2, q = lane & 3;
    bool diag = (tm == tn);

    uint32_t sbase = smem_u32(smem);

    // ---- global -> shared via cp.async, split-K double commit (K halves) ----
    const uint4* __restrict__ src = (const uint4*)g_nhat; // 16 x 16B chunks per row
    #pragma unroll
    for (int h = 0; h < 2; ++h) {
        #pragma unroll
        for (int it = 0; it < 4; ++it) {     // 128 rows x 8 chunks per half per tile
            int idx = it * 256 + tid;        // 0..1023
            int r = idx >> 3, kv = (idx & 7) + h * 8;
            uint32_t off = (uint32_t)(r * 256 + kv * 16);
            uint32_t sw = off ^ ((uint32_t)(r & 7) << 4);
            cp_async16(sbase + sw, src + (size_t)(tm * 128 + r) * 16 + kv);
            if (!diag)
                cp_async16(sbase + TILEB + sw, src + (size_t)(tn * 128 + r) * 16 + kv);
        }
        asm volatile("cp.async.commit_group;" ::: "memory");
    }

    uint32_t sA = sbase;
    uint32_t sB = diag ? sA : (sA + TILEB);

    float acc[4][4][4];
    #pragma unroll
    for (int i = 0; i < 4; ++i)
        #pragma unroll
        for (int j = 0; j < 4; ++j)
            #pragma unroll
            for (int x = 0; x < 4; ++x) acc[i][j][x] = 0.f;

    int l7 = lane & 7;
    int ra_base = wm * 64 + l7 + ((lane >> 3) & 1) * 8;  // A rows
    int ka_base = (lane >> 4) * 16;                      // A 16B sub-chunk of 32B k-step
    int rb_base = wn * 32 + l7 + (lane >> 4) * 8;        // B n-rows
    int kb_base = ((lane >> 3) & 1) * 16;                // B 16B sub-chunk

    #pragma unroll
    for (int half = 0; half < 2; ++half) {
        if (half == 0) asm volatile("cp.async.wait_group 1;" ::: "memory");
        else           asm volatile("cp.async.wait_group 0;" ::: "memory");
        __syncthreads();
        #pragma unroll
        for (int k2 = 0; k2 < 4; ++k2) {                 // k-step = 32 fp8 = 32 bytes
            int kk = half * 4 + k2;
            uint32_t af[4][4];
            #pragma unroll
            for (int i = 0; i < 4; ++i) {
                int r = ra_base + i * 16;
                uint32_t off = (uint32_t)(r * 256 + kk * 32 + ka_base);
                ldsm_x4(sA + (off ^ ((uint32_t)(r & 7) << 4)), af[i]);
            }
            uint32_t bf[2][4];
            #pragma unroll
            for (int j2 = 0; j2 < 2; ++j2) {
                int r = rb_base + j2 * 16;
                uint32_t off = (uint32_t)(r * 256 + kk * 32 + kb_base);
                ldsm_x4(sB + (off ^ ((uint32_t)(r & 7) << 4)), bf[j2]);
            }
            #pragma unroll
            for (int i = 0; i < 4; ++i)
                #pragma unroll
                for (int j = 0; j < 4; ++j)
                    mma16832_e4m3(acc[i][j], af[i], &bf[j >> 1][(j & 1) * 2]);
        }
    }
    __syncthreads();   // smem tiles no longer needed; reuse for reductions

    float* rAcc = (float*)smem;        // 128 row partials (tm rows)
    float* cAcc = rAcc + 128;          // 128 col partials (tn rows, via symmetry)
    ((float*)smem)[tid] = 0.f;
    __syncthreads();

    float rs[4][2], cs[4][2];
    #pragma unroll
    for (int i = 0; i < 4; ++i) { rs[i][0] = 0.f; rs[i][1] = 0.f; }
    #pragma unroll
    for (int j = 0; j < 4; ++j) { cs[j][0] = 0.f; cs[j][1] = 0.f; }

    if (!diag) {
        // ---- hot path: packed f16x2 exp; acc already = (2/T)*log2e * s ----
        uint32_t rsp[4][2], csp[4];
        #pragma unroll
        for (int i = 0; i < 4; ++i) { rsp[i][0] = 0u; rsp[i][1] = 0u; }
        #pragma unroll
        for (int j = 0; j < 4; ++j) csp[j] = 0u;

        #pragma unroll
        for (int i = 0; i < 4; ++i) {
            #pragma unroll
            for (int j = 0; j < 4; ++j) {
                uint32_t e0 = h2ex2(packh2(acc[i][j][0], acc[i][j][1]));  // row R0: (C0,C1)
                uint32_t e1 = h2ex2(packh2(acc[i][j][2], acc[i][j][3]));  // row R1: (C0,C1)
                rsp[i][0] = hadd2(rsp[i][0], e0);
                rsp[i][1] = hadd2(rsp[i][1], e1);
                csp[j] = hadd2(csp[j], hadd2(e0, e1));
            }
        }
        #pragma unroll
        for (int i = 0; i < 4; ++i) {
            float lo, hi;
            unpackh2(rsp[i][0], lo, hi);  rs[i][0] = lo + hi;
            unpackh2(rsp[i][1], lo, hi);  rs[i][1] = lo + hi;
        }
        #pragma unroll
        for (int j = 0; j < 4; ++j)
            unpackh2(csp[j], cs[j][0], cs[j][1]);
    } else {
        // ---- diagonal tiles (64 of 2080): scalar f32, mask self-diagonal ----
        #pragma unroll
        for (int i = 0; i < 4; ++i) {
            int R0 = wm * 64 + i * 16 + g, R1 = R0 + 8;
            #pragma unroll
            for (int j = 0; j < 4; ++j) {
                int C0 = wn * 32 + j * 8 + 2 * q, C1 = C0 + 1;
                float e00 = ex2f(acc[i][j][0]);
                float e01 = ex2f(acc[i][j][1]);
                float e10 = ex2f(acc[i][j][2]);
                float e11 = ex2f(acc[i][j][3]);
                if (R0 == C0) e00 = 0.f;
                if (R0 == C1) e01 = 0.f;
                if (R1 == C0) e10 = 0.f;
                if (R1 == C1) e11 = 0.f;
                rs[i][0] += e00 + e01;  rs[i][1] += e10 + e11;
            }
        }
    }
    // row partials: lanes sharing g share rows -> reduce over q
    #pragma unroll
    for (int i = 0; i < 4; ++i)
        #pragma unroll
        for (int h = 0; h < 2; ++h) {
            float v = rs[i][h];
            v += __shfl_xor_sync(0xFFFFFFFFu, v, 1);
            v += __shfl_xor_sync(0xFFFFFFFFu, v, 2);
            if (q == 0) atomicAdd(&rAcc[wm * 64 + i * 16 + g + h * 8], v);
        }
    // col partials: lanes sharing q share cols -> reduce over g (off-diagonal tiles)
    if (!diag) {
        #pragma unroll
        for (int j = 0; j < 4; ++j)
            #pragma unroll
            for (int h = 0; h < 2; ++h) {
                float v = cs[j][h];
                v += __shfl_xor_sync(0xFFFFFFFFu, v, 4);
                v += __shfl_xor_sync(0xFFFFFFFFu, v, 8);
                v += __shfl_xor_sync(0xFFFFFFFFu, v, 16);
                if (g == 0) atomicAdd(&cAcc[wn * 32 + j * 8 + 2 * q + h], v);
            }
    }
    __syncthreads();
    if (tid < 128) {
        atomicAdd(&g_rowsum[tm * 128 + tid], rAcc[tid]);
        if (!diag) atomicAdd(&g_rowsum[tn * 128 + tid], cAcc[tid]);
    }
}

// ---------------- kernel 3 (fused): per-row log - pos, full reduce, write loss -------
__global__ void k_tail(float* __restrict__ out) {
    __shared__ float sh[32];
    int tid = threadIdx.x;                   // 1024 threads, 8 rows each
    float v = 0.f;
    #pragma unroll
    for (int it = 0; it < 8; ++it) {
        int r = tid + it * 1024;
        v += __logf(g_rowsum[r]) - 2.0f * g_pos[r & (NPAIRS - 1)];
    }
    #pragma unroll
    for (int o = 16; o; o >>= 1) v += __shfl_xor_sync(0xFFFFFFFFu, v, o);
    if ((tid & 31) == 0) sh[tid >> 5] = v;
    __syncthreads();
    if (tid < 32) {
        float s = sh[tid];
        #pragma unroll
        for (int o = 16; o; o >>= 1) s += __shfl_xor_sync(0xFFFFFFFFu, s, o);
        if (tid == 0) out[0] = s / (float)TWO_N;
    }
}

// ---------------- launch ----------------
extern "C" void kernel_launch(void* const* d_in, const int* in_sizes, int n_in,
                              void* d_out, int out_size) {
    const float* zis = (const float*)d_in[0];
    const float* zjs = (const float*)d_in[1];
    float* out = (float*)d_out;

    cudaFuncSetAttribute(k_gemm, cudaFuncAttributeMaxDynamicSharedMemorySize, SMEM_TOTAL);

    k_norm<<<512, 256>>>(zis, zjs);
    k_gemm<<<NTRI, 256, SMEM_TOTAL>>>();
    k_tail<<<1, 1024>>>(out);
}